// round 15
// baseline (speedup 1.0000x reference)
#include <cuda_runtime.h>
#include <cuda_fp16.h>
#include <math.h>
#include <stdint.h>

// Problem constants
#define BATCH 4
#define TSZ   1024
#define DIM   1024
#define NHEAD 16
#define HDIM  64
#define C3    (3 * DIM)

// Scratch (allocation-free: __device__ globals) — fp16 pipeline
__device__ __half g_xh[BATCH * TSZ * DIM];
__device__ __half g_wqkvh[C3 * DIM];
__device__ __half g_wprojh[DIM * DIM];
__device__ __half g_qkvh[BATCH * TSZ * C3];   // [B,T,3C]
__device__ __half g_atth[BATCH * TSZ * DIM];  // [B,T,C]

// ---------------------------------------------------------------------------
// helpers
// ---------------------------------------------------------------------------
__device__ __forceinline__ void mma_f16(float c[4], const uint32_t a[4],
                                        uint32_t b0, uint32_t b1) {
    asm volatile(
        "mma.sync.aligned.m16n8k16.row.col.f32.f16.f16.f32 "
        "{%0,%1,%2,%3}, {%4,%5,%6,%7}, {%8,%9}, {%0,%1,%2,%3};"
        : "+f"(c[0]), "+f"(c[1]), "+f"(c[2]), "+f"(c[3])
        : "r"(a[0]), "r"(a[1]), "r"(a[2]), "r"(a[3]), "r"(b0), "r"(b1));
}

__device__ __forceinline__ void ldsm_x4(uint32_t& r0, uint32_t& r1, uint32_t& r2,
                                        uint32_t& r3, uint32_t saddr) {
    asm volatile(
        "ldmatrix.sync.aligned.m8n8.x4.shared.b16 {%0,%1,%2,%3}, [%4];"
        : "=r"(r0), "=r"(r1), "=r"(r2), "=r"(r3)
        : "r"(saddr));
}

__device__ __forceinline__ void ldsm_x4_trans(uint32_t& r0, uint32_t& r1,
                                              uint32_t& r2, uint32_t& r3,
                                              uint32_t saddr) {
    asm volatile(
        "ldmatrix.sync.aligned.m8n8.x4.trans.shared.b16 {%0,%1,%2,%3}, [%4];"
        : "=r"(r0), "=r"(r1), "=r"(r2), "=r"(r3)
        : "r"(saddr));
}

__device__ __forceinline__ uint4 f8_to_h8(float4 a, float4 b) {
    __half2 h0 = __floats2half2_rn(a.x, a.y);
    __half2 h1 = __floats2half2_rn(a.z, a.w);
    __half2 h2 = __floats2half2_rn(b.x, b.y);
    __half2 h3 = __floats2half2_rn(b.z, b.w);
    uint4 u;
    u.x = *(uint32_t*)&h0; u.y = *(uint32_t*)&h1;
    u.z = *(uint32_t*)&h2; u.w = *(uint32_t*)&h3;
    return u;
}

#define CP_ASYNC16(dst, src) \
    asm volatile("cp.async.cg.shared.global [%0], [%1], 16;" :: "r"(dst), "l"(src))
#define CP_COMMIT() asm volatile("cp.async.commit_group;")
#define CP_WAIT0()  asm volatile("cp.async.wait_group 0;")
#define CP_WAIT1()  asm volatile("cp.async.wait_group 1;")

// fp16 m16n8k16 fragment lane->address components (offsets in halves):
#define A16_ROW(lane) ((lane) & 15)
#define A16_KOF(lane) (((lane) >> 4) * 8)
#define B16_ROW(lane) (((lane) & 7) + ((lane) >> 4) * 8)
#define B16_KOF(lane) ((((lane) >> 3) & 1) * 8)

// ---------------------------------------------------------------------------
// fused fp32 -> fp16 conversion of all three inputs (8 elts/thread)
// ---------------------------------------------------------------------------
#define N_X  (BATCH * TSZ * DIM)   // 4194304
#define N_WQ (C3 * DIM)            // 3145728
#define N_WP (DIM * DIM)           // 1048576

__global__ __launch_bounds__(256)
void cvt3_f32_f16(const float* __restrict__ x, const float* __restrict__ wq,
                  const float* __restrict__ wp, __half* __restrict__ xh,
                  __half* __restrict__ wqh, __half* __restrict__ wph) {
    long i = ((long)blockIdx.x * 256 + threadIdx.x) * 8;
    const float* src;
    __half* dst;
    if (i < N_X) {
        src = x + i; dst = xh + i;
    } else if (i < (long)N_X + N_WQ) {
        src = wq + (i - N_X); dst = wqh + (i - N_X);
    } else {
        src = wp + (i - N_X - N_WQ); dst = wph + (i - N_X - N_WQ);
    }
    float4 a = *(const float4*)(src);
    float4 b = *(const float4*)(src + 4);
    *(uint4*)(dst) = f8_to_h8(a, b);
}

// ---------------------------------------------------------------------------
// FP16 GEMM "wide" — BK=64 (R13-proven): block 128x256, 512 thr = 16 warps
// (4x4), warp tile 32x64, 2-stage cp.async, stride 72. For QKV.
// ---------------------------------------------------------------------------
#define WBK 64
#define WSTR 72
#define WSA_H (128 * WSTR)
#define WSB_H (256 * WSTR)
#define WSTAGE_H (WSA_H + WSB_H)
#define GEMMW_SMEM (2 * WSTAGE_H * 2)   // 110592 bytes

__global__ __launch_bounds__(512, 1)
void f16_gemm_wide(const __half* __restrict__ A, const __half* __restrict__ B,
                   __half* __restrict__ C, int M, int N, int K) {
    extern __shared__ __half gsm[];

    const int tid  = threadIdx.x;
    const int lane = tid & 31;
    const int warp = tid >> 5;         // 0..15
    const int g = lane >> 2;
    const int t = lane & 3;
    const int wm = (warp >> 2) * 32;
    const int wn = (warp & 3) * 64;
    const int bm = blockIdx.y * 128;
    const int bn = blockIdx.x * 256;

    const int srow = tid >> 2;         // 0..127
    const int sch  = (tid & 3) * 16;   // 0,16,32,48

    const __half* Ap  = A + (size_t)(bm + srow) * K + sch;
    const __half* Bp0 = B + (size_t)(bn + srow) * K + sch;
    const __half* Bp1 = B + (size_t)(bn + 128 + srow) * K + sch;

    const uint32_t smem0 = (uint32_t)__cvta_generic_to_shared(gsm);
    const uint32_t dR  = 2u * (srow * WSTR + sch);
    const uint32_t dB1 = 2u * ((128 + srow) * WSTR + sch);

    const int ar = A16_ROW(lane), ak = A16_KOF(lane);
    const int br = B16_ROW(lane), bk = B16_KOF(lane);

    float acc[2][8][4];
#pragma unroll
    for (int i = 0; i < 2; i++)
#pragma unroll
        for (int j = 0; j < 8; j++)
#pragma unroll
            for (int q = 0; q < 4; q++) acc[i][j][q] = 0.f;

#define GW_STAGE(slot, kt)                                                     \
    do {                                                                       \
        const uint32_t so = smem0 + 2u * (uint32_t)(slot) * WSTAGE_H;          \
        CP_ASYNC16(so + dR, Ap + (kt) * WBK);                                  \
        CP_ASYNC16(so + dR + 16, Ap + (kt) * WBK + 8);                         \
        CP_ASYNC16(so + 2u * WSA_H + dR, Bp0 + (kt) * WBK);                    \
        CP_ASYNC16(so + 2u * WSA_H + dR + 16, Bp0 + (kt) * WBK + 8);           \
        CP_ASYNC16(so + 2u * WSA_H + dB1, Bp1 + (kt) * WBK);                   \
        CP_ASYNC16(so + 2u * WSA_H + dB1 + 16, Bp1 + (kt) * WBK + 8);          \
        CP_COMMIT();                                                           \
    } while (0)

    const int NT = K / WBK;   // 16
    GW_STAGE(0, 0);

    for (int kt = 0; kt < NT; kt++) {
        const int buf = kt & 1;
        if (kt + 1 < NT) {
            GW_STAGE(buf ^ 1, kt + 1);
            CP_WAIT1();
        } else {
            CP_WAIT0();
        }
        __syncthreads();

        const uint32_t aA = smem0 + 2u * (uint32_t)buf * WSTAGE_H;
        const uint32_t aB = aA + 2u * WSA_H;
#pragma unroll
        for (int kk = 0; kk < 4; kk++) {
            uint32_t af[2][4];
#pragma unroll
            for (int mt = 0; mt < 2; mt++)
                ldsm_x4(af[mt][0], af[mt][1], af[mt][2], af[mt][3],
                        aA + 2u * ((wm + mt * 16 + ar) * WSTR + kk * 16 + ak));
#pragma unroll
            for (int p = 0; p < 4; p++) {
                uint32_t b0, b1, b2, b3;
                ldsm_x4(b0, b1, b2, b3,
                        aB + 2u * ((wn + p * 16 + br) * WSTR + kk * 16 + bk));
#pragma unroll
                for (int mt = 0; mt < 2; mt++) {
                    mma_f16(acc[mt][2 * p],     af[mt], b0, b1);
                    mma_f16(acc[mt][2 * p + 1], af[mt], b2, b3);
                }
            }
        }
        __syncthreads();
    }

    // fp16 epilogue
#pragma unroll
    for (int mt = 0; mt < 2; mt++) {
#pragma unroll
        for (int nt = 0; nt < 8; nt++) {
            const float* a4 = acc[mt][nt];
            const int row = bm + wm + mt * 16 + g;
            const int col = bn + wn + nt * 8 + 2 * t;
            __half2 v0 = __floats2half2_rn(a4[0], a4[1]);
            __half2 v1 = __floats2half2_rn(a4[2], a4[3]);
            *(uint32_t*)&C[(size_t)row * N + col] = *(uint32_t*)&v0;
            *(uint32_t*)&C[(size_t)(row + 8) * N + col] = *(uint32_t*)&v1;
        }
    }
}

// ---------------------------------------------------------------------------
// FP16 GEMM "proj" — 64x128 tiles, 128 thr = 4 warps (2x2), warp tile 32x64,
// BK=32, 2-stage cp.async, 3 CTAs/SM. fp32 output + bias.
// Staging: 6 cp.async/thread — A row (2x16B) + two B rows (2x16B each).
// ---------------------------------------------------------------------------
#define BK 32
#define ASTR 40
#define PA_H (64 * ASTR)
#define PB_H (128 * ASTR)
#define PSTAGE_H (PA_H + PB_H)
#define GEMMP_SMEM (2 * PSTAGE_H * 2)   // 30720 bytes

__global__ __launch_bounds__(128, 3)
void f16_gemm_proj(const __half* __restrict__ A, const __half* __restrict__ B,
                   const float* __restrict__ bias, float* __restrict__ C,
                   int M, int N, int K) {
    extern __shared__ __half gsm[];

    const int tid  = threadIdx.x;
    const int lane = tid & 31;
    const int warp = tid >> 5;         // 0..3
    const int g = lane >> 2;
    const int t = lane & 3;
    const int wm = (warp >> 1) * 32;   // 0,32
    const int wn = (warp & 1) * 64;    // 0,64
    const int bm = blockIdx.y * 64;
    const int bn = blockIdx.x * 128;

    // staging: 2 threads per row; each thread covers 16 halves (2 x 16B)
    const int srow = tid >> 1;         // 0..63
    const int sch  = (tid & 1) * 16;   // 0,16

    const __half* Ap  = A + (size_t)(bm + srow) * K + sch;
    const __half* Bp0 = B + (size_t)(bn + srow) * K + sch;
    const __half* Bp1 = B + (size_t)(bn + 64 + srow) * K + sch;

    const uint32_t smem0 = (uint32_t)__cvta_generic_to_shared(gsm);
    const uint32_t dA  = 2u * (srow * ASTR + sch);
    const uint32_t dB0 = 2u * (srow * ASTR + sch);
    const uint32_t dB1 = 2u * ((64 + srow) * ASTR + sch);

    const int ar = A16_ROW(lane), ak = A16_KOF(lane);
    const int br = B16_ROW(lane), bk = B16_KOF(lane);

    float acc[2][8][4];
#pragma unroll
    for (int i = 0; i < 2; i++)
#pragma unroll
        for (int j = 0; j < 8; j++)
#pragma unroll
            for (int q = 0; q < 4; q++) acc[i][j][q] = 0.f;

#define GP_STAGE(slot, kt)                                                     \
    do {                                                                       \
        const uint32_t so = smem0 + 2u * (uint32_t)(slot) * PSTAGE_H;          \
        CP_ASYNC16(so + dA, Ap + (kt) * BK);                                   \
        CP_ASYNC16(so + dA + 16, Ap + (kt) * BK + 8);                          \
        CP_ASYNC16(so + 2u * PA_H + dB0, Bp0 + (kt) * BK);                     \
        CP_ASYNC16(so + 2u * PA_H + dB0 + 16, Bp0 + (kt) * BK + 8);            \
        CP_ASYNC16(so + 2u * PA_H + dB1, Bp1 + (kt) * BK);                     \
        CP_ASYNC16(so + 2u * PA_H + dB1 + 16, Bp1 + (kt) * BK + 8);            \
        CP_COMMIT();                                                           \
    } while (0)

    const int NT = K / BK;
    GP_STAGE(0, 0);

    for (int kt = 0; kt < NT; kt++) {
        const int buf = kt & 1;
        if (kt + 1 < NT) {
            GP_STAGE(buf ^ 1, kt + 1);
            CP_WAIT1();
        } else {
            CP_WAIT0();
        }
        __syncthreads();

        const uint32_t aA = smem0 + 2u * (uint32_t)buf * PSTAGE_H;
        const uint32_t aB = aA + 2u * PA_H;
#pragma unroll
        for (int kk = 0; kk < 2; kk++) {
            uint32_t af[2][4];
#pragma unroll
            for (int mt = 0; mt < 2; mt++)
                ldsm_x4(af[mt][0], af[mt][1], af[mt][2], af[mt][3],
                        aA + 2u * ((wm + mt * 16 + ar) * ASTR + kk * 16 + ak));
#pragma unroll
            for (int p = 0; p < 4; p++) {
                uint32_t b0, b1, b2, b3;
                ldsm_x4(b0, b1, b2, b3,
                        aB + 2u * ((wn + p * 16 + br) * ASTR + kk * 16 + bk));
#pragma unroll
                for (int mt = 0; mt < 2; mt++) {
                    mma_f16(acc[mt][2 * p],     af[mt], b0, b1);
                    mma_f16(acc[mt][2 * p + 1], af[mt], b2, b3);
                }
            }
        }
        __syncthreads();
    }

    // fp32 epilogue + bias
#pragma unroll
    for (int mt = 0; mt < 2; mt++) {
#pragma unroll
        for (int nt = 0; nt < 8; nt++) {
            const float* a4 = acc[mt][nt];
            const int row = bm + wm + mt * 16 + g;
            const int col = bn + wn + nt * 8 + 2 * t;
            float bx = bias[col], by = bias[col + 1];
            float2 v0 = {a4[0] + bx, a4[1] + by};
            float2 v1 = {a4[2] + bx, a4[3] + by};
            *(float2*)(C + (size_t)row * N + col) = v0;
            *(float2*)(C + (size_t)(row + 8) * N + col) = v1;
        }
    }
}

// ---------------------------------------------------------------------------
// FP16 flash attention (R12-proven) — register-resident P.
// 256 threads = 8 warps, 128 q-rows, 16 kv-tiles of 64, 2-stage cp.async KV.
// ---------------------------------------------------------------------------
#define FSTR 72
#define KV_H (64 * FSTR)
#define FLASH_HALVES (4 * KV_H + 128 * FSTR)
#define FLASH_SMEM   (FLASH_HALVES * 2)

__global__ __launch_bounds__(256, 2)
void flash_f16(const __half* __restrict__ qkv, __half* __restrict__ att) {
    extern __shared__ __half fsm[];

    const int tid  = threadIdx.x;
    const int lane = tid & 31;
    const int warp = tid >> 5;
    const int g = lane >> 2;
    const int t = lane & 3;
    const int bh = blockIdx.y;
    const int b = bh >> 4;
    const int h = bh & 15;
    const int q0 = blockIdx.x * 128;
    const size_t base = (size_t)b * TSZ * C3;
    const int hoff = h * HDIM;
    const float qscale = 0.125f * 1.44269504088896340736f;  // scale * log2(e)

    const uint32_t smem0 = (uint32_t)__cvta_generic_to_shared(fsm);
    const uint32_t sKb[2] = {smem0, smem0 + 2u * 2 * KV_H};
    const uint32_t sVb[2] = {smem0 + 2u * KV_H, smem0 + 2u * 3 * KV_H};
    const uint32_t sQb = smem0 + 2u * 4 * KV_H;

    const int ar = A16_ROW(lane), ak = A16_KOF(lane);
    const int br = B16_ROW(lane), bk = B16_KOF(lane);
    const int vj = (lane & 7) + ((lane >> 3) & 1) * 8;
    const int vd = (lane >> 4) * 8;

    // Q staging (group 1)
#pragma unroll
    for (int it = 0; it < 4; it++) {
        const int i = tid + it * 256;
        const int r = i >> 3, c8 = (i & 7) * 8;
        CP_ASYNC16(sQb + 2u * (r * FSTR + c8),
                   qkv + base + (size_t)(q0 + r) * C3 + hoff + c8);
    }
    CP_COMMIT();

#define KV_STAGE(bufi, kt)                                                     \
    do {                                                                       \
        const uint32_t soK = sKb[bufi];                                        \
        const uint32_t soV = sVb[bufi];                                        \
        const __half* srcb = qkv + base + (size_t)((kt) * 64) * C3 + hoff;     \
        _Pragma("unroll")                                                      \
        for (int it = 0; it < 2; it++) {                                       \
            const int i = tid + it * 256;                                      \
            const int r = i >> 3, c8 = (i & 7) * 8;                            \
            CP_ASYNC16(soK + 2u * (r * FSTR + c8),                             \
                       srcb + (size_t)r * C3 + DIM + c8);                      \
            CP_ASYNC16(soV + 2u * (r * FSTR + c8),                             \
                       srcb + (size_t)r * C3 + 2 * DIM + c8);                  \
        }                                                                      \
        CP_COMMIT();                                                           \
    } while (0)

    KV_STAGE(0, 0);

    // Wait for Q (KV group 0 may stay pending), load Q fragments
    CP_WAIT1();
    __syncthreads();
    uint32_t aq[4][4];
#pragma unroll
    for (int kk = 0; kk < 4; kk++)
        ldsm_x4(aq[kk][0], aq[kk][1], aq[kk][2], aq[kk][3],
                sQb + 2u * ((warp * 16 + ar) * FSTR + kk * 16 + ak));

    float accO[8][4];
#pragma unroll
    for (int i = 0; i < 8; i++)
#pragma unroll
        for (int j = 0; j < 4; j++) accO[i][j] = 0.f;
    float m0 = -INFINITY, m1 = -INFINITY, l0 = 0.f, l1 = 0.f;

    for (int kt = 0; kt < 16; kt++) {
        const int buf = kt & 1;
        if (kt + 1 < 16) {
            KV_STAGE(buf ^ 1, kt + 1);
            CP_WAIT1();
        } else {
            CP_WAIT0();
        }
        __syncthreads();

        // S = Q * K^T
        float accS[8][4];
#pragma unroll
        for (int i = 0; i < 8; i++)
#pragma unroll
            for (int j = 0; j < 4; j++) accS[i][j] = 0.f;
#pragma unroll
        for (int kk = 0; kk < 4; kk++) {
#pragma unroll
            for (int p = 0; p < 4; p++) {
                uint32_t b0, b1, b2, b3;
                ldsm_x4(b0, b1, b2, b3,
                        sKb[buf] + 2u * ((p * 16 + br) * FSTR + kk * 16 + bk));
                mma_f16(accS[2 * p],     aq[kk], b0, b1);
                mma_f16(accS[2 * p + 1], aq[kk], b2, b3);
            }
        }
#pragma unroll
        for (int nt = 0; nt < 8; nt++) {
            accS[nt][0] *= qscale; accS[nt][1] *= qscale;
            accS[nt][2] *= qscale; accS[nt][3] *= qscale;
        }

        // Online softmax (rows g, g+8), base-2 domain
        float r0 = -INFINITY, r1 = -INFINITY;
#pragma unroll
        for (int nt = 0; nt < 8; nt++) {
            r0 = fmaxf(r0, fmaxf(accS[nt][0], accS[nt][1]));
            r1 = fmaxf(r1, fmaxf(accS[nt][2], accS[nt][3]));
        }
        r0 = fmaxf(r0, __shfl_xor_sync(0xffffffffu, r0, 1));
        r0 = fmaxf(r0, __shfl_xor_sync(0xffffffffu, r0, 2));
        r1 = fmaxf(r1, __shfl_xor_sync(0xffffffffu, r1, 1));
        r1 = fmaxf(r1, __shfl_xor_sync(0xffffffffu, r1, 2));
        const float mn0 = fmaxf(m0, r0);
        const float mn1 = fmaxf(m1, r1);
        const float al0 = exp2f(m0 - mn0);
        const float al1 = exp2f(m1 - mn1);
        float rs0 = 0.f, rs1 = 0.f;

        // P as A-fragments directly (C-frag of S == A-frag of P identity)
        uint32_t phA[8], phB[8];
#pragma unroll
        for (int nt = 0; nt < 8; nt++) {
            __half2 h01 = __floats2half2_rn(exp2f(accS[nt][0] - mn0),
                                            exp2f(accS[nt][1] - mn0));
            __half2 h23 = __floats2half2_rn(exp2f(accS[nt][2] - mn1),
                                            exp2f(accS[nt][3] - mn1));
            float2 f01 = __half22float2(h01);
            float2 f23 = __half22float2(h23);
            rs0 += f01.x + f01.y;
            rs1 += f23.x + f23.y;
            phA[nt] = *(uint32_t*)&h01;
            phB[nt] = *(uint32_t*)&h23;
        }
        rs0 += __shfl_xor_sync(0xffffffffu, rs0, 1);
        rs0 += __shfl_xor_sync(0xffffffffu, rs0, 2);
        rs1 += __shfl_xor_sync(0xffffffffu, rs1, 1);
        rs1 += __shfl_xor_sync(0xffffffffu, rs1, 2);
        l0 = l0 * al0 + rs0;
        l1 = l1 * al1 + rs1;
        m0 = mn0; m1 = mn1;
#pragma unroll
        for (int nt = 0; nt < 8; nt++) {
            accO[nt][0] *= al0; accO[nt][1] *= al0;
            accO[nt][2] *= al1; accO[nt][3] *= al1;
        }

        // O += P V (P from registers; V: B-frag via ldmatrix.trans)
#pragma unroll
        for (int kk = 0; kk < 4; kk++) {
            uint32_t ap[4];
            ap[0] = phA[2 * kk];
            ap[1] = phB[2 * kk];
            ap[2] = phA[2 * kk + 1];
            ap[3] = phB[2 * kk + 1];
#pragma unroll
            for (int p = 0; p < 4; p++) {
                uint32_t v0, v1, v2, v3;
                ldsm_x4_trans(v0, v1, v2, v3,
                              sVb[buf] + 2u * ((kk * 16 + vj) * FSTR + p * 16 + vd));
                mma_f16(accO[2 * p],     ap, v0, v1);
                mma_f16(accO[2 * p + 1], ap, v2, v3);
            }
        }
        __syncthreads();  // readers done before buf overwritten next iter
    }

    // Epilogue: normalize, write fp16 att [B,T,C]
    const float inv0 = 1.f / l0;
    const float inv1 = 1.f / l1;
    const int r0w = q0 + warp * 16 + g;
    __half* o0 = att + (size_t)b * TSZ * DIM + (size_t)r0w * DIM + hoff;
    __half* o1 = o0 + (size_t)8 * DIM;
#pragma unroll
    for (int nt = 0; nt < 8; nt++) {
        __half2 v0 = __floats2half2_rn(accO[nt][0] * inv0, accO[nt][1] * inv0);
        __half2 v1 = __floats2half2_rn(accO[nt][2] * inv1, accO[nt][3] * inv1);
        *(uint32_t*)&o0[nt * 8 + 2 * t] = *(uint32_t*)&v0;
        *(uint32_t*)&o1[nt * 8 + 2 * t] = *(uint32_t*)&v1;
    }
}

// ---------------------------------------------------------------------------
extern "C" void kernel_launch(void* const* d_in, const int* in_sizes, int n_in,
                              void* d_out, int out_size) {
    const float* x     = (const float*)d_in[0];  // [4,1024,1024]
    const float* Wqkv  = (const float*)d_in[1];  // [3072,1024]
    const float* Wproj = (const float*)d_in[2];  // [1024,1024]
    const float* bproj = (const float*)d_in[3];  // [1024]
    float* out = (float*)d_out;                  // [4,1024,1024]

    __half *xh, *wqkvh, *wprojh, *qkvh, *atth;
    cudaGetSymbolAddress((void**)&xh, g_xh);
    cudaGetSymbolAddress((void**)&wqkvh, g_wqkvh);
    cudaGetSymbolAddress((void**)&wprojh, g_wprojh);
    cudaGetSymbolAddress((void**)&qkvh, g_qkvh);
    cudaGetSymbolAddress((void**)&atth, g_atth);

    cudaFuncSetAttribute(f16_gemm_wide,
                         cudaFuncAttributeMaxDynamicSharedMemorySize, GEMMW_SMEM);
    cudaFuncSetAttribute(f16_gemm_proj,
                         cudaFuncAttributeMaxDynamicSharedMemorySize, GEMMP_SMEM);
    cudaFuncSetAttribute(flash_f16,
                         cudaFuncAttributeMaxDynamicSharedMemorySize, FLASH_SMEM);

    // 0) fused fp32 -> fp16 conversion (x, Wqkv, Wproj)
    cvt3_f32_f16<<<(N_X + N_WQ + N_WP) / 2048, 256>>>(x, Wqkv, Wproj,
                                                      xh, wqkvh, wprojh);

    // 1) QKV projection -> fp16: [4096,1024] x [3072,1024]^T -> [4096,3072]
    f16_gemm_wide<<<dim3(C3 / 256, (BATCH * TSZ) / 128), 512, GEMMW_SMEM>>>(
        xh, wqkvh, qkvh, BATCH * TSZ, C3, DIM);

    // 2) Attention (fp16 in/out, register-resident P)
    flash_f16<<<dim3(TSZ / 128, BATCH * NHEAD), 256, FLASH_SMEM>>>(qkvh, atth);

    // 3) Output projection + bias -> fp32 out (64x128 tiles, 3 CTAs/SM)
    f16_gemm_proj<<<dim3(DIM / 128, (BATCH * TSZ) / 64), 128, GEMMP_SMEM>>>(
        atth, wprojh, bproj, out, BATCH * TSZ, DIM, DIM);
}

// round 16
// speedup vs baseline: 1.0189x; 1.0189x over previous
#include <cuda_runtime.h>
#include <cuda_fp16.h>
#include <math.h>
#include <stdint.h>

// Problem constants
#define BATCH 4
#define TSZ   1024
#define DIM   1024
#define NHEAD 16
#define HDIM  64
#define C3    (3 * DIM)

// Scratch (allocation-free: __device__ globals) — fp16 pipeline
__device__ __half g_xh[BATCH * TSZ * DIM];
__device__ __half g_wqkvh[C3 * DIM];
__device__ __half g_wprojh[DIM * DIM];
__device__ __half g_qkvh[BATCH * TSZ * C3];   // [B,T,3C]
__device__ __half g_atth[BATCH * TSZ * DIM];  // [B,T,C]

// ---------------------------------------------------------------------------
// helpers
// ---------------------------------------------------------------------------
__device__ __forceinline__ void mma_f16(float c[4], const uint32_t a[4],
                                        uint32_t b0, uint32_t b1) {
    asm volatile(
        "mma.sync.aligned.m16n8k16.row.col.f32.f16.f16.f32 "
        "{%0,%1,%2,%3}, {%4,%5,%6,%7}, {%8,%9}, {%0,%1,%2,%3};"
        : "+f"(c[0]), "+f"(c[1]), "+f"(c[2]), "+f"(c[3])
        : "r"(a[0]), "r"(a[1]), "r"(a[2]), "r"(a[3]), "r"(b0), "r"(b1));
}

__device__ __forceinline__ void ldsm_x4(uint32_t& r0, uint32_t& r1, uint32_t& r2,
                                        uint32_t& r3, uint32_t saddr) {
    asm volatile(
        "ldmatrix.sync.aligned.m8n8.x4.shared.b16 {%0,%1,%2,%3}, [%4];"
        : "=r"(r0), "=r"(r1), "=r"(r2), "=r"(r3)
        : "r"(saddr));
}

__device__ __forceinline__ void ldsm_x4_trans(uint32_t& r0, uint32_t& r1,
                                              uint32_t& r2, uint32_t& r3,
                                              uint32_t saddr) {
    asm volatile(
        "ldmatrix.sync.aligned.m8n8.x4.trans.shared.b16 {%0,%1,%2,%3}, [%4];"
        : "=r"(r0), "=r"(r1), "=r"(r2), "=r"(r3)
        : "r"(saddr));
}

__device__ __forceinline__ uint4 f8_to_h8(float4 a, float4 b) {
    __half2 h0 = __floats2half2_rn(a.x, a.y);
    __half2 h1 = __floats2half2_rn(a.z, a.w);
    __half2 h2 = __floats2half2_rn(b.x, b.y);
    __half2 h3 = __floats2half2_rn(b.z, b.w);
    uint4 u;
    u.x = *(uint32_t*)&h0; u.y = *(uint32_t*)&h1;
    u.z = *(uint32_t*)&h2; u.w = *(uint32_t*)&h3;
    return u;
}

#define CP_ASYNC16(dst, src) \
    asm volatile("cp.async.cg.shared.global [%0], [%1], 16;" :: "r"(dst), "l"(src))
#define CP_COMMIT() asm volatile("cp.async.commit_group;")
#define CP_WAIT0()  asm volatile("cp.async.wait_group 0;")
#define CP_WAIT1()  asm volatile("cp.async.wait_group 1;")

// fp16 m16n8k16 fragment lane->address components (offsets in halves):
#define A16_ROW(lane) ((lane) & 15)
#define A16_KOF(lane) (((lane) >> 4) * 8)
#define B16_ROW(lane) (((lane) & 7) + ((lane) >> 4) * 8)
#define B16_KOF(lane) ((((lane) >> 3) & 1) * 8)

// ---------------------------------------------------------------------------
// fused fp32 -> fp16 conversion of all three inputs (8 elts/thread)
// ---------------------------------------------------------------------------
#define N_X  (BATCH * TSZ * DIM)   // 4194304
#define N_WQ (C3 * DIM)            // 3145728
#define N_WP (DIM * DIM)           // 1048576

__global__ __launch_bounds__(256)
void cvt3_f32_f16(const float* __restrict__ x, const float* __restrict__ wq,
                  const float* __restrict__ wp, __half* __restrict__ xh,
                  __half* __restrict__ wqh, __half* __restrict__ wph) {
    long i = ((long)blockIdx.x * 256 + threadIdx.x) * 8;
    const float* src;
    __half* dst;
    if (i < N_X) {
        src = x + i; dst = xh + i;
    } else if (i < (long)N_X + N_WQ) {
        src = wq + (i - N_X); dst = wqh + (i - N_X);
    } else {
        src = wp + (i - N_X - N_WQ); dst = wph + (i - N_X - N_WQ);
    }
    float4 a = *(const float4*)(src);
    float4 b = *(const float4*)(src + 4);
    *(uint4*)(dst) = f8_to_h8(a, b);
}

// ---------------------------------------------------------------------------
// FP16 GEMM "wide" — BK=64 (R13-proven): block 128x256, 512 thr = 16 warps
// (4x4), warp tile 32x64, 2-stage cp.async, stride 72. For QKV.
// ---------------------------------------------------------------------------
#define WBK 64
#define WSTR 72
#define WSA_H (128 * WSTR)
#define WSB_H (256 * WSTR)
#define WSTAGE_H (WSA_H + WSB_H)
#define GEMMW_SMEM (2 * WSTAGE_H * 2)   // 110592 bytes

__global__ __launch_bounds__(512, 1)
void f16_gemm_wide(const __half* __restrict__ A, const __half* __restrict__ B,
                   __half* __restrict__ C, int M, int N, int K) {
    extern __shared__ __half gsm[];

    const int tid  = threadIdx.x;
    const int lane = tid & 31;
    const int warp = tid >> 5;         // 0..15
    const int g = lane >> 2;
    const int t = lane & 3;
    const int wm = (warp >> 2) * 32;
    const int wn = (warp & 3) * 64;
    const int bm = blockIdx.y * 128;
    const int bn = blockIdx.x * 256;

    const int srow = tid >> 2;         // 0..127
    const int sch  = (tid & 3) * 16;   // 0,16,32,48

    const __half* Ap  = A + (size_t)(bm + srow) * K + sch;
    const __half* Bp0 = B + (size_t)(bn + srow) * K + sch;
    const __half* Bp1 = B + (size_t)(bn + 128 + srow) * K + sch;

    const uint32_t smem0 = (uint32_t)__cvta_generic_to_shared(gsm);
    const uint32_t dR  = 2u * (srow * WSTR + sch);
    const uint32_t dB1 = 2u * ((128 + srow) * WSTR + sch);

    const int ar = A16_ROW(lane), ak = A16_KOF(lane);
    const int br = B16_ROW(lane), bk = B16_KOF(lane);

    float acc[2][8][4];
#pragma unroll
    for (int i = 0; i < 2; i++)
#pragma unroll
        for (int j = 0; j < 8; j++)
#pragma unroll
            for (int q = 0; q < 4; q++) acc[i][j][q] = 0.f;

#define GW_STAGE(slot, kt)                                                     \
    do {                                                                       \
        const uint32_t so = smem0 + 2u * (uint32_t)(slot) * WSTAGE_H;          \
        CP_ASYNC16(so + dR, Ap + (kt) * WBK);                                  \
        CP_ASYNC16(so + dR + 16, Ap + (kt) * WBK + 8);                         \
        CP_ASYNC16(so + 2u * WSA_H + dR, Bp0 + (kt) * WBK);                    \
        CP_ASYNC16(so + 2u * WSA_H + dR + 16, Bp0 + (kt) * WBK + 8);           \
        CP_ASYNC16(so + 2u * WSA_H + dB1, Bp1 + (kt) * WBK);                   \
        CP_ASYNC16(so + 2u * WSA_H + dB1 + 16, Bp1 + (kt) * WBK + 8);          \
        CP_COMMIT();                                                           \
    } while (0)

    const int NT = K / WBK;   // 16
    GW_STAGE(0, 0);

    for (int kt = 0; kt < NT; kt++) {
        const int buf = kt & 1;
        if (kt + 1 < NT) {
            GW_STAGE(buf ^ 1, kt + 1);
            CP_WAIT1();
        } else {
            CP_WAIT0();
        }
        __syncthreads();

        const uint32_t aA = smem0 + 2u * (uint32_t)buf * WSTAGE_H;
        const uint32_t aB = aA + 2u * WSA_H;
#pragma unroll
        for (int kk = 0; kk < 4; kk++) {
            uint32_t af[2][4];
#pragma unroll
            for (int mt = 0; mt < 2; mt++)
                ldsm_x4(af[mt][0], af[mt][1], af[mt][2], af[mt][3],
                        aA + 2u * ((wm + mt * 16 + ar) * WSTR + kk * 16 + ak));
#pragma unroll
            for (int p = 0; p < 4; p++) {
                uint32_t b0, b1, b2, b3;
                ldsm_x4(b0, b1, b2, b3,
                        aB + 2u * ((wn + p * 16 + br) * WSTR + kk * 16 + bk));
#pragma unroll
                for (int mt = 0; mt < 2; mt++) {
                    mma_f16(acc[mt][2 * p],     af[mt], b0, b1);
                    mma_f16(acc[mt][2 * p + 1], af[mt], b2, b3);
                }
            }
        }
        __syncthreads();
    }

    // fp16 epilogue
#pragma unroll
    for (int mt = 0; mt < 2; mt++) {
#pragma unroll
        for (int nt = 0; nt < 8; nt++) {
            const float* a4 = acc[mt][nt];
            const int row = bm + wm + mt * 16 + g;
            const int col = bn + wn + nt * 8 + 2 * t;
            __half2 v0 = __floats2half2_rn(a4[0], a4[1]);
            __half2 v1 = __floats2half2_rn(a4[2], a4[3]);
            *(uint32_t*)&C[(size_t)row * N + col] = *(uint32_t*)&v0;
            *(uint32_t*)&C[(size_t)(row + 8) * N + col] = *(uint32_t*)&v1;
        }
    }
}

// ---------------------------------------------------------------------------
// FP16 GEMM "square" — BK=64: block 128x128, 256 thr = 8 warps (4x2),
// warp tile 32x64, 2-stage cp.async, stride 72, 2 CTAs/SM (72KB smem/CTA).
// fp32 output + bias. For proj.
// ---------------------------------------------------------------------------
#define SBK 64
#define SSTR 72
#define SSA_H (128 * SSTR)
#define SSTAGE_H (2 * SSA_H)
#define GEMMS_SMEM (2 * SSTAGE_H * 2)   // 73728 bytes

__global__ __launch_bounds__(256, 2)
void f16_gemm_sq(const __half* __restrict__ A, const __half* __restrict__ B,
                 const float* __restrict__ bias, float* __restrict__ C,
                 int M, int N, int K) {
    extern __shared__ __half gsm[];

    const int tid  = threadIdx.x;
    const int lane = tid & 31;
    const int warp = tid >> 5;         // 0..7
    const int g = lane >> 2;
    const int t = lane & 3;
    const int wm = (warp >> 1) * 32;   // 0,32,64,96
    const int wn = (warp & 1) * 64;    // 0,64
    const int bm = blockIdx.y * 128;
    const int bn = blockIdx.x * 128;

    // staging: 2 threads/row, each covers 32 halves (4 x 16B)
    const int srow = tid >> 1;         // 0..127
    const int sch  = (tid & 1) * 32;   // 0,32

    const __half* Ap = A + (size_t)(bm + srow) * K + sch;
    const __half* Bp = B + (size_t)(bn + srow) * K + sch;

    const uint32_t smem0 = (uint32_t)__cvta_generic_to_shared(gsm);
    const uint32_t dR = 2u * (srow * SSTR + sch);

    const int ar = A16_ROW(lane), ak = A16_KOF(lane);
    const int br = B16_ROW(lane), bk = B16_KOF(lane);

    float acc[2][8][4];
#pragma unroll
    for (int i = 0; i < 2; i++)
#pragma unroll
        for (int j = 0; j < 8; j++)
#pragma unroll
            for (int q = 0; q < 4; q++) acc[i][j][q] = 0.f;

#define GS_STAGE(slot, kt)                                                     \
    do {                                                                       \
        const uint32_t so = smem0 + 2u * (uint32_t)(slot) * SSTAGE_H;          \
        CP_ASYNC16(so + dR,      Ap + (kt) * SBK);                             \
        CP_ASYNC16(so + dR + 16, Ap + (kt) * SBK + 8);                         \
        CP_ASYNC16(so + dR + 32, Ap + (kt) * SBK + 16);                        \
        CP_ASYNC16(so + dR + 48, Ap + (kt) * SBK + 24);                        \
        CP_ASYNC16(so + 2u * SSA_H + dR,      Bp + (kt) * SBK);                \
        CP_ASYNC16(so + 2u * SSA_H + dR + 16, Bp + (kt) * SBK + 8);            \
        CP_ASYNC16(so + 2u * SSA_H + dR + 32, Bp + (kt) * SBK + 16);           \
        CP_ASYNC16(so + 2u * SSA_H + dR + 48, Bp + (kt) * SBK + 24);           \
        CP_COMMIT();                                                           \
    } while (0)

    const int NT = K / SBK;   // 16
    GS_STAGE(0, 0);

    for (int kt = 0; kt < NT; kt++) {
        const int buf = kt & 1;
        if (kt + 1 < NT) {
            GS_STAGE(buf ^ 1, kt + 1);
            CP_WAIT1();
        } else {
            CP_WAIT0();
        }
        __syncthreads();

        const uint32_t aA = smem0 + 2u * (uint32_t)buf * SSTAGE_H;
        const uint32_t aB = aA + 2u * SSA_H;
#pragma unroll
        for (int kk = 0; kk < 4; kk++) {   // four k16 per SBK=64
            uint32_t af[2][4];
#pragma unroll
            for (int mt = 0; mt < 2; mt++)
                ldsm_x4(af[mt][0], af[mt][1], af[mt][2], af[mt][3],
                        aA + 2u * ((wm + mt * 16 + ar) * SSTR + kk * 16 + ak));
#pragma unroll
            for (int p = 0; p < 4; p++) {
                uint32_t b0, b1, b2, b3;
                ldsm_x4(b0, b1, b2, b3,
                        aB + 2u * ((wn + p * 16 + br) * SSTR + kk * 16 + bk));
#pragma unroll
                for (int mt = 0; mt < 2; mt++) {
                    mma_f16(acc[mt][2 * p],     af[mt], b0, b1);
                    mma_f16(acc[mt][2 * p + 1], af[mt], b2, b3);
                }
            }
        }
        __syncthreads();
    }

    // fp32 epilogue + bias
#pragma unroll
    for (int mt = 0; mt < 2; mt++) {
#pragma unroll
        for (int nt = 0; nt < 8; nt++) {
            const float* a4 = acc[mt][nt];
            const int row = bm + wm + mt * 16 + g;
            const int col = bn + wn + nt * 8 + 2 * t;
            float bx = bias[col], by = bias[col + 1];
            float2 v0 = {a4[0] + bx, a4[1] + by};
            float2 v1 = {a4[2] + bx, a4[3] + by};
            *(float2*)(C + (size_t)row * N + col) = v0;
            *(float2*)(C + (size_t)(row + 8) * N + col) = v1;
        }
    }
}

// ---------------------------------------------------------------------------
// FP16 flash attention (R12/R13-proven) — register-resident P.
// 256 threads = 8 warps, 128 q-rows, 16 kv-tiles of 64, 2-stage cp.async KV.
// ---------------------------------------------------------------------------
#define FSTR 72
#define KV_H (64 * FSTR)
#define FLASH_HALVES (4 * KV_H + 128 * FSTR)
#define FLASH_SMEM   (FLASH_HALVES * 2)

__global__ __launch_bounds__(256, 2)
void flash_f16(const __half* __restrict__ qkv, __half* __restrict__ att) {
    extern __shared__ __half fsm[];

    const int tid  = threadIdx.x;
    const int lane = tid & 31;
    const int warp = tid >> 5;
    const int g = lane >> 2;
    const int t = lane & 3;
    const int bh = blockIdx.y;
    const int b = bh >> 4;
    const int h = bh & 15;
    const int q0 = blockIdx.x * 128;
    const size_t base = (size_t)b * TSZ * C3;
    const int hoff = h * HDIM;
    const float qscale = 0.125f * 1.44269504088896340736f;  // scale * log2(e)

    const uint32_t smem0 = (uint32_t)__cvta_generic_to_shared(fsm);
    const uint32_t sKb[2] = {smem0, smem0 + 2u * 2 * KV_H};
    const uint32_t sVb[2] = {smem0 + 2u * KV_H, smem0 + 2u * 3 * KV_H};
    const uint32_t sQb = smem0 + 2u * 4 * KV_H;

    const int ar = A16_ROW(lane), ak = A16_KOF(lane);
    const int br = B16_ROW(lane), bk = B16_KOF(lane);
    const int vj = (lane & 7) + ((lane >> 3) & 1) * 8;
    const int vd = (lane >> 4) * 8;

    // Q staging (group 1)
#pragma unroll
    for (int it = 0; it < 4; it++) {
        const int i = tid + it * 256;
        const int r = i >> 3, c8 = (i & 7) * 8;
        CP_ASYNC16(sQb + 2u * (r * FSTR + c8),
                   qkv + base + (size_t)(q0 + r) * C3 + hoff + c8);
    }
    CP_COMMIT();

#define KV_STAGE(bufi, kt)                                                     \
    do {                                                                       \
        const uint32_t soK = sKb[bufi];                                        \
        const uint32_t soV = sVb[bufi];                                        \
        const __half* srcb = qkv + base + (size_t)((kt) * 64) * C3 + hoff;     \
        _Pragma("unroll")                                                      \
        for (int it = 0; it < 2; it++) {                                       \
            const int i = tid + it * 256;                                      \
            const int r = i >> 3, c8 = (i & 7) * 8;                            \
            CP_ASYNC16(soK + 2u * (r * FSTR + c8),                             \
                       srcb + (size_t)r * C3 + DIM + c8);                      \
            CP_ASYNC16(soV + 2u * (r * FSTR + c8),                             \
                       srcb + (size_t)r * C3 + 2 * DIM + c8);                  \
        }                                                                      \
        CP_COMMIT();                                                           \
    } while (0)

    KV_STAGE(0, 0);

    // Wait for Q (KV group 0 may stay pending), load Q fragments
    CP_WAIT1();
    __syncthreads();
    uint32_t aq[4][4];
#pragma unroll
    for (int kk = 0; kk < 4; kk++)
        ldsm_x4(aq[kk][0], aq[kk][1], aq[kk][2], aq[kk][3],
                sQb + 2u * ((warp * 16 + ar) * FSTR + kk * 16 + ak));

    float accO[8][4];
#pragma unroll
    for (int i = 0; i < 8; i++)
#pragma unroll
        for (int j = 0; j < 4; j++) accO[i][j] = 0.f;
    float m0 = -INFINITY, m1 = -INFINITY, l0 = 0.f, l1 = 0.f;

    for (int kt = 0; kt < 16; kt++) {
        const int buf = kt & 1;
        if (kt + 1 < 16) {
            KV_STAGE(buf ^ 1, kt + 1);
            CP_WAIT1();
        } else {
            CP_WAIT0();
        }
        __syncthreads();

        // S = Q * K^T
        float accS[8][4];
#pragma unroll
        for (int i = 0; i < 8; i++)
#pragma unroll
            for (int j = 0; j < 4; j++) accS[i][j] = 0.f;
#pragma unroll
        for (int kk = 0; kk < 4; kk++) {
#pragma unroll
            for (int p = 0; p < 4; p++) {
                uint32_t b0, b1, b2, b3;
                ldsm_x4(b0, b1, b2, b3,
                        sKb[buf] + 2u * ((p * 16 + br) * FSTR + kk * 16 + bk));
                mma_f16(accS[2 * p],     aq[kk], b0, b1);
                mma_f16(accS[2 * p + 1], aq[kk], b2, b3);
            }
        }
#pragma unroll
        for (int nt = 0; nt < 8; nt++) {
            accS[nt][0] *= qscale; accS[nt][1] *= qscale;
            accS[nt][2] *= qscale; accS[nt][3] *= qscale;
        }

        // Online softmax (rows g, g+8), base-2 domain
        float r0 = -INFINITY, r1 = -INFINITY;
#pragma unroll
        for (int nt = 0; nt < 8; nt++) {
            r0 = fmaxf(r0, fmaxf(accS[nt][0], accS[nt][1]));
            r1 = fmaxf(r1, fmaxf(accS[nt][2], accS[nt][3]));
        }
        r0 = fmaxf(r0, __shfl_xor_sync(0xffffffffu, r0, 1));
        r0 = fmaxf(r0, __shfl_xor_sync(0xffffffffu, r0, 2));
        r1 = fmaxf(r1, __shfl_xor_sync(0xffffffffu, r1, 1));
        r1 = fmaxf(r1, __shfl_xor_sync(0xffffffffu, r1, 2));
        const float mn0 = fmaxf(m0, r0);
        const float mn1 = fmaxf(m1, r1);
        const float al0 = exp2f(m0 - mn0);
        const float al1 = exp2f(m1 - mn1);
        float rs0 = 0.f, rs1 = 0.f;

        // P as A-fragments directly (C-frag of S == A-frag of P identity)
        uint32_t phA[8], phB[8];
#pragma unroll
        for (int nt = 0; nt < 8; nt++) {
            __half2 h01 = __floats2half2_rn(exp2f(accS[nt][0] - mn0),
                                            exp2f(accS[nt][1] - mn0));
            __half2 h23 = __floats2half2_rn(exp2f(accS[nt][2] - mn1),
                                            exp2f(accS[nt][3] - mn1));
            float2 f01 = __half22float2(h01);
            float2 f23 = __half22float2(h23);
            rs0 += f01.x + f01.y;
            rs1 += f23.x + f23.y;
            phA[nt] = *(uint32_t*)&h01;
            phB[nt] = *(uint32_t*)&h23;
        }
        rs0 += __shfl_xor_sync(0xffffffffu, rs0, 1);
        rs0 += __shfl_xor_sync(0xffffffffu, rs0, 2);
        rs1 += __shfl_xor_sync(0xffffffffu, rs1, 1);
        rs1 += __shfl_xor_sync(0xffffffffu, rs1, 2);
        l0 = l0 * al0 + rs0;
        l1 = l1 * al1 + rs1;
        m0 = mn0; m1 = mn1;
#pragma unroll
        for (int nt = 0; nt < 8; nt++) {
            accO[nt][0] *= al0; accO[nt][1] *= al0;
            accO[nt][2] *= al1; accO[nt][3] *= al1;
        }

        // O += P V (P from registers; V: B-frag via ldmatrix.trans)
#pragma unroll
        for (int kk = 0; kk < 4; kk++) {
            uint32_t ap[4];
            ap[0] = phA[2 * kk];
            ap[1] = phB[2 * kk];
            ap[2] = phA[2 * kk + 1];
            ap[3] = phB[2 * kk + 1];
#pragma unroll
            for (int p = 0; p < 4; p++) {
                uint32_t v0, v1, v2, v3;
                ldsm_x4_trans(v0, v1, v2, v3,
                              sVb[buf] + 2u * ((kk * 16 + vj) * FSTR + p * 16 + vd));
                mma_f16(accO[2 * p],     ap, v0, v1);
                mma_f16(accO[2 * p + 1], ap, v2, v3);
            }
        }
        __syncthreads();  // readers done before buf overwritten next iter
    }

    // Epilogue: normalize, write fp16 att [B,T,C]
    const float inv0 = 1.f / l0;
    const float inv1 = 1.f / l1;
    const int r0w = q0 + warp * 16 + g;
    __half* o0 = att + (size_t)b * TSZ * DIM + (size_t)r0w * DIM + hoff;
    __half* o1 = o0 + (size_t)8 * DIM;
#pragma unroll
    for (int nt = 0; nt < 8; nt++) {
        __half2 v0 = __floats2half2_rn(accO[nt][0] * inv0, accO[nt][1] * inv0);
        __half2 v1 = __floats2half2_rn(accO[nt][2] * inv1, accO[nt][3] * inv1);
        *(uint32_t*)&o0[nt * 8 + 2 * t] = *(uint32_t*)&v0;
        *(uint32_t*)&o1[nt * 8 + 2 * t] = *(uint32_t*)&v1;
    }
}

// ---------------------------------------------------------------------------
extern "C" void kernel_launch(void* const* d_in, const int* in_sizes, int n_in,
                              void* d_out, int out_size) {
    const float* x     = (const float*)d_in[0];  // [4,1024,1024]
    const float* Wqkv  = (const float*)d_in[1];  // [3072,1024]
    const float* Wproj = (const float*)d_in[2];  // [1024,1024]
    const float* bproj = (const float*)d_in[3];  // [1024]
    float* out = (float*)d_out;                  // [4,1024,1024]

    __half *xh, *wqkvh, *wprojh, *qkvh, *atth;
    cudaGetSymbolAddress((void**)&xh, g_xh);
    cudaGetSymbolAddress((void**)&wqkvh, g_wqkvh);
    cudaGetSymbolAddress((void**)&wprojh, g_wprojh);
    cudaGetSymbolAddress((void**)&qkvh, g_qkvh);
    cudaGetSymbolAddress((void**)&atth, g_atth);

    cudaFuncSetAttribute(f16_gemm_wide,
                         cudaFuncAttributeMaxDynamicSharedMemorySize, GEMMW_SMEM);
    cudaFuncSetAttribute(f16_gemm_sq,
                         cudaFuncAttributeMaxDynamicSharedMemorySize, GEMMS_SMEM);
    cudaFuncSetAttribute(flash_f16,
                         cudaFuncAttributeMaxDynamicSharedMemorySize, FLASH_SMEM);

    // 0) fused fp32 -> fp16 conversion (x, Wqkv, Wproj)
    cvt3_f32_f16<<<(N_X + N_WQ + N_WP) / 2048, 256>>>(x, Wqkv, Wproj,
                                                      xh, wqkvh, wprojh);

    // 1) QKV projection -> fp16: [4096,1024] x [3072,1024]^T -> [4096,3072]
    f16_gemm_wide<<<dim3(C3 / 256, (BATCH * TSZ) / 128), 512, GEMMW_SMEM>>>(
        xh, wqkvh, qkvh, BATCH * TSZ, C3, DIM);

    // 2) Attention (fp16 in/out, register-resident P)
    flash_f16<<<dim3(TSZ / 128, BATCH * NHEAD), 256, FLASH_SMEM>>>(qkvh, atth);

    // 3) Output projection + bias -> fp32 out (square 128x128, BK=64, 2 CTA/SM)
    f16_gemm_sq<<<dim3(DIM / 128, (BATCH * TSZ) / 128), 256, GEMMS_SMEM>>>(
        atth, wprojh, bproj, out, BATCH * TSZ, DIM, DIM);
}

// round 17
// speedup vs baseline: 1.0663x; 1.0465x over previous
#include <cuda_runtime.h>
#include <cuda_fp16.h>
#include <math.h>
#include <stdint.h>

// Problem constants
#define BATCH 4
#define TSZ   1024
#define DIM   1024
#define NHEAD 16
#define HDIM  64
#define C3    (3 * DIM)

// Scratch (allocation-free: __device__ globals) — fp16 pipeline
__device__ __half g_xh[BATCH * TSZ * DIM];
__device__ __half g_wqkvh[C3 * DIM];
__device__ __half g_wprojh[DIM * DIM];
__device__ __half g_qkvh[BATCH * TSZ * C3];   // [B,T,3C]
__device__ __half g_atth[BATCH * TSZ * DIM];  // [B,T,C]

// ---------------------------------------------------------------------------
// helpers
// ---------------------------------------------------------------------------
__device__ __forceinline__ void mma_f16(float c[4], const uint32_t a[4],
                                        uint32_t b0, uint32_t b1) {
    asm volatile(
        "mma.sync.aligned.m16n8k16.row.col.f32.f16.f16.f32 "
        "{%0,%1,%2,%3}, {%4,%5,%6,%7}, {%8,%9}, {%0,%1,%2,%3};"
        : "+f"(c[0]), "+f"(c[1]), "+f"(c[2]), "+f"(c[3])
        : "r"(a[0]), "r"(a[1]), "r"(a[2]), "r"(a[3]), "r"(b0), "r"(b1));
}

__device__ __forceinline__ void ldsm_x4(uint32_t& r0, uint32_t& r1, uint32_t& r2,
                                        uint32_t& r3, uint32_t saddr) {
    asm volatile(
        "ldmatrix.sync.aligned.m8n8.x4.shared.b16 {%0,%1,%2,%3}, [%4];"
        : "=r"(r0), "=r"(r1), "=r"(r2), "=r"(r3)
        : "r"(saddr));
}

__device__ __forceinline__ void ldsm_x4_trans(uint32_t& r0, uint32_t& r1,
                                              uint32_t& r2, uint32_t& r3,
                                              uint32_t saddr) {
    asm volatile(
        "ldmatrix.sync.aligned.m8n8.x4.trans.shared.b16 {%0,%1,%2,%3}, [%4];"
        : "=r"(r0), "=r"(r1), "=r"(r2), "=r"(r3)
        : "r"(saddr));
}

__device__ __forceinline__ uint4 f8_to_h8(float4 a, float4 b) {
    __half2 h0 = __floats2half2_rn(a.x, a.y);
    __half2 h1 = __floats2half2_rn(a.z, a.w);
    __half2 h2 = __floats2half2_rn(b.x, b.y);
    __half2 h3 = __floats2half2_rn(b.z, b.w);
    uint4 u;
    u.x = *(uint32_t*)&h0; u.y = *(uint32_t*)&h1;
    u.z = *(uint32_t*)&h2; u.w = *(uint32_t*)&h3;
    return u;
}

#define CP_ASYNC16(dst, src) \
    asm volatile("cp.async.cg.shared.global [%0], [%1], 16;" :: "r"(dst), "l"(src))
#define CP_COMMIT() asm volatile("cp.async.commit_group;")
#define CP_WAIT0()  asm volatile("cp.async.wait_group 0;")
#define CP_WAIT1()  asm volatile("cp.async.wait_group 1;")

// fp16 m16n8k16 fragment lane->address components (offsets in halves):
#define A16_ROW(lane) ((lane) & 15)
#define A16_KOF(lane) (((lane) >> 4) * 8)
#define B16_ROW(lane) (((lane) & 7) + ((lane) >> 4) * 8)
#define B16_KOF(lane) ((((lane) >> 3) & 1) * 8)

// ---------------------------------------------------------------------------
// fused fp32 -> fp16 conversion of all three inputs (8 elts/thread)
// ---------------------------------------------------------------------------
#define N_X  (BATCH * TSZ * DIM)   // 4194304
#define N_WQ (C3 * DIM)            // 3145728
#define N_WP (DIM * DIM)           // 1048576

__global__ __launch_bounds__(256)
void cvt3_f32_f16(const float* __restrict__ x, const float* __restrict__ wq,
                  const float* __restrict__ wp, __half* __restrict__ xh,
                  __half* __restrict__ wqh, __half* __restrict__ wph) {
    long i = ((long)blockIdx.x * 256 + threadIdx.x) * 8;
    const float* src;
    __half* dst;
    if (i < N_X) {
        src = x + i; dst = xh + i;
    } else if (i < (long)N_X + N_WQ) {
        src = wq + (i - N_X); dst = wqh + (i - N_X);
    } else {
        src = wp + (i - N_X - N_WQ); dst = wph + (i - N_X - N_WQ);
    }
    float4 a = *(const float4*)(src);
    float4 b = *(const float4*)(src + 4);
    *(uint4*)(dst) = f8_to_h8(a, b);
}

// ---------------------------------------------------------------------------
// FP16 GEMM "wide" — BK=64 (R13-proven): block 128x256, 512 thr = 16 warps
// (4x4), warp tile 32x64, 2-stage cp.async, stride 72. For QKV.
// ---------------------------------------------------------------------------
#define WBK 64
#define WSTR 72
#define WSA_H (128 * WSTR)
#define WSB_H (256 * WSTR)
#define WSTAGE_H (WSA_H + WSB_H)
#define GEMMW_SMEM (2 * WSTAGE_H * 2)   // 110592 bytes

__global__ __launch_bounds__(512, 1)
void f16_gemm_wide(const __half* __restrict__ A, const __half* __restrict__ B,
                   __half* __restrict__ C, int M, int N, int K) {
    extern __shared__ __half gsm[];

    const int tid  = threadIdx.x;
    const int lane = tid & 31;
    const int warp = tid >> 5;         // 0..15
    const int g = lane >> 2;
    const int t = lane & 3;
    const int wm = (warp >> 2) * 32;
    const int wn = (warp & 3) * 64;
    const int bm = blockIdx.y * 128;
    const int bn = blockIdx.x * 256;

    const int srow = tid >> 2;         // 0..127
    const int sch  = (tid & 3) * 16;   // 0,16,32,48

    const __half* Ap  = A + (size_t)(bm + srow) * K + sch;
    const __half* Bp0 = B + (size_t)(bn + srow) * K + sch;
    const __half* Bp1 = B + (size_t)(bn + 128 + srow) * K + sch;

    const uint32_t smem0 = (uint32_t)__cvta_generic_to_shared(gsm);
    const uint32_t dR  = 2u * (srow * WSTR + sch);
    const uint32_t dB1 = 2u * ((128 + srow) * WSTR + sch);

    const int ar = A16_ROW(lane), ak = A16_KOF(lane);
    const int br = B16_ROW(lane), bk = B16_KOF(lane);

    float acc[2][8][4];
#pragma unroll
    for (int i = 0; i < 2; i++)
#pragma unroll
        for (int j = 0; j < 8; j++)
#pragma unroll
            for (int q = 0; q < 4; q++) acc[i][j][q] = 0.f;

#define GW_STAGE(slot, kt)                                                     \
    do {                                                                       \
        const uint32_t so = smem0 + 2u * (uint32_t)(slot) * WSTAGE_H;          \
        CP_ASYNC16(so + dR, Ap + (kt) * WBK);                                  \
        CP_ASYNC16(so + dR + 16, Ap + (kt) * WBK + 8);                         \
        CP_ASYNC16(so + 2u * WSA_H + dR, Bp0 + (kt) * WBK);                    \
        CP_ASYNC16(so + 2u * WSA_H + dR + 16, Bp0 + (kt) * WBK + 8);           \
        CP_ASYNC16(so + 2u * WSA_H + dB1, Bp1 + (kt) * WBK);                   \
        CP_ASYNC16(so + 2u * WSA_H + dB1 + 16, Bp1 + (kt) * WBK + 8);          \
        CP_COMMIT();                                                           \
    } while (0)

    const int NT = K / WBK;   // 16
    GW_STAGE(0, 0);

    for (int kt = 0; kt < NT; kt++) {
        const int buf = kt & 1;
        if (kt + 1 < NT) {
            GW_STAGE(buf ^ 1, kt + 1);
            CP_WAIT1();
        } else {
            CP_WAIT0();
        }
        __syncthreads();

        const uint32_t aA = smem0 + 2u * (uint32_t)buf * WSTAGE_H;
        const uint32_t aB = aA + 2u * WSA_H;
#pragma unroll
        for (int kk = 0; kk < 4; kk++) {
            uint32_t af[2][4];
#pragma unroll
            for (int mt = 0; mt < 2; mt++)
                ldsm_x4(af[mt][0], af[mt][1], af[mt][2], af[mt][3],
                        aA + 2u * ((wm + mt * 16 + ar) * WSTR + kk * 16 + ak));
#pragma unroll
            for (int p = 0; p < 4; p++) {
                uint32_t b0, b1, b2, b3;
                ldsm_x4(b0, b1, b2, b3,
                        aB + 2u * ((wn + p * 16 + br) * WSTR + kk * 16 + bk));
#pragma unroll
                for (int mt = 0; mt < 2; mt++) {
                    mma_f16(acc[mt][2 * p],     af[mt], b0, b1);
                    mma_f16(acc[mt][2 * p + 1], af[mt], b2, b3);
                }
            }
        }
        __syncthreads();
    }

    // fp16 epilogue
#pragma unroll
    for (int mt = 0; mt < 2; mt++) {
#pragma unroll
        for (int nt = 0; nt < 8; nt++) {
            const float* a4 = acc[mt][nt];
            const int row = bm + wm + mt * 16 + g;
            const int col = bn + wn + nt * 8 + 2 * t;
            __half2 v0 = __floats2half2_rn(a4[0], a4[1]);
            __half2 v1 = __floats2half2_rn(a4[2], a4[3]);
            *(uint32_t*)&C[(size_t)row * N + col] = *(uint32_t*)&v0;
            *(uint32_t*)&C[(size_t)(row + 8) * N + col] = *(uint32_t*)&v1;
        }
    }
}

// ---------------------------------------------------------------------------
// FP16 GEMM "square" (R13-proven): block 128x128, 256 thr = 8 warps (4x2),
// warp tile 32x64, BK=32, 2-stage cp.async, 2 CTAs/SM. fp32 out + bias. Proj.
// ---------------------------------------------------------------------------
#define BK 32
#define ASTR 40
#define SSA_H (128 * ASTR)
#define SSTAGE_H (2 * SSA_H)
#define GEMMS_SMEM (2 * SSTAGE_H * 2)

__global__ __launch_bounds__(256, 2)
void f16_gemm_sq(const __half* __restrict__ A, const __half* __restrict__ B,
                 const float* __restrict__ bias, float* __restrict__ C,
                 int M, int N, int K) {
    extern __shared__ __half gsm[];

    const int tid  = threadIdx.x;
    const int lane = tid & 31;
    const int warp = tid >> 5;         // 0..7
    const int g = lane >> 2;
    const int t = lane & 3;
    const int wm = (warp >> 1) * 32;
    const int wn = (warp & 1) * 64;
    const int bm = blockIdx.y * 128;
    const int bn = blockIdx.x * 128;

    const int srow = tid >> 1;         // 0..127
    const int sch  = (tid & 1) * 16;   // 0,16

    const __half* Ap = A + (size_t)(bm + srow) * K + sch;
    const __half* Bp = B + (size_t)(bn + srow) * K + sch;

    const uint32_t smem0 = (uint32_t)__cvta_generic_to_shared(gsm);
    const uint32_t dR = 2u * (srow * ASTR + sch);

    const int ar = A16_ROW(lane), ak = A16_KOF(lane);
    const int br = B16_ROW(lane), bk = B16_KOF(lane);

    float acc[2][8][4];
#pragma unroll
    for (int i = 0; i < 2; i++)
#pragma unroll
        for (int j = 0; j < 8; j++)
#pragma unroll
            for (int q = 0; q < 4; q++) acc[i][j][q] = 0.f;

#define GS_STAGE(slot, kt)                                                     \
    do {                                                                       \
        const uint32_t so = smem0 + 2u * (uint32_t)(slot) * SSTAGE_H;          \
        CP_ASYNC16(so + dR, Ap + (kt) * BK);                                   \
        CP_ASYNC16(so + dR + 16, Ap + (kt) * BK + 8);                          \
        CP_ASYNC16(so + 2u * SSA_H + dR, Bp + (kt) * BK);                      \
        CP_ASYNC16(so + 2u * SSA_H + dR + 16, Bp + (kt) * BK + 8);             \
        CP_COMMIT();                                                           \
    } while (0)

    const int NT = K / BK;
    GS_STAGE(0, 0);

    for (int kt = 0; kt < NT; kt++) {
        const int buf = kt & 1;
        if (kt + 1 < NT) {
            GS_STAGE(buf ^ 1, kt + 1);
            CP_WAIT1();
        } else {
            CP_WAIT0();
        }
        __syncthreads();

        const uint32_t aA = smem0 + 2u * (uint32_t)buf * SSTAGE_H;
        const uint32_t aB = aA + 2u * SSA_H;
#pragma unroll
        for (int kk = 0; kk < 2; kk++) {
            uint32_t af[2][4];
#pragma unroll
            for (int mt = 0; mt < 2; mt++)
                ldsm_x4(af[mt][0], af[mt][1], af[mt][2], af[mt][3],
                        aA + 2u * ((wm + mt * 16 + ar) * ASTR + kk * 16 + ak));
#pragma unroll
            for (int p = 0; p < 4; p++) {
                uint32_t b0, b1, b2, b3;
                ldsm_x4(b0, b1, b2, b3,
                        aB + 2u * ((wn + p * 16 + br) * ASTR + kk * 16 + bk));
#pragma unroll
                for (int mt = 0; mt < 2; mt++) {
                    mma_f16(acc[mt][2 * p],     af[mt], b0, b1);
                    mma_f16(acc[mt][2 * p + 1], af[mt], b2, b3);
                }
            }
        }
        __syncthreads();
    }

    // fp32 epilogue + bias
#pragma unroll
    for (int mt = 0; mt < 2; mt++) {
#pragma unroll
        for (int nt = 0; nt < 8; nt++) {
            const float* a4 = acc[mt][nt];
            const int row = bm + wm + mt * 16 + g;
            const int col = bn + wn + nt * 8 + 2 * t;
            float bx = bias[col], by = bias[col + 1];
            float2 v0 = {a4[0] + bx, a4[1] + by};
            float2 v1 = {a4[2] + bx, a4[3] + by};
            *(float2*)(C + (size_t)row * N + col) = v0;
            *(float2*)(C + (size_t)(row + 8) * N + col) = v1;
        }
    }
}

// ---------------------------------------------------------------------------
// FP16 flash attention — register-resident P, 64-q-row CTAs for fine-grained
// wave balance: 128 threads = 4 warps x 16 rows, 1024 CTAs, 4 CTAs/SM target.
// 16 kv-tiles of 64, 2-stage cp.async KV.
// smem: kvbuf0{K,V}, kvbuf1{K,V} each [64][72], then sQ [64][72].
// ---------------------------------------------------------------------------
#define FSTR 72
#define KV_H (64 * FSTR)
#define FLASH_HALVES (4 * KV_H + 64 * FSTR)
#define FLASH_SMEM   (FLASH_HALVES * 2)   // 46080 bytes

__global__ __launch_bounds__(128, 4)
void flash_f16(const __half* __restrict__ qkv, __half* __restrict__ att) {
    extern __shared__ __half fsm[];

    const int tid  = threadIdx.x;
    const int lane = tid & 31;
    const int warp = tid >> 5;          // 0..3
    const int g = lane >> 2;
    const int t = lane & 3;
    const int bh = blockIdx.y;
    const int b = bh >> 4;
    const int h = bh & 15;
    const int q0 = blockIdx.x * 64;
    const size_t base = (size_t)b * TSZ * C3;
    const int hoff = h * HDIM;
    const float qscale = 0.125f * 1.44269504088896340736f;  // scale * log2(e)

    const uint32_t smem0 = (uint32_t)__cvta_generic_to_shared(fsm);
    const uint32_t sKb[2] = {smem0, smem0 + 2u * 2 * KV_H};
    const uint32_t sVb[2] = {smem0 + 2u * KV_H, smem0 + 2u * 3 * KV_H};
    const uint32_t sQb = smem0 + 2u * 4 * KV_H;

    const int ar = A16_ROW(lane), ak = A16_KOF(lane);
    const int br = B16_ROW(lane), bk = B16_KOF(lane);
    const int vj = (lane & 7) + ((lane >> 3) & 1) * 8;
    const int vd = (lane >> 4) * 8;

    // Q staging (group 1): 64 rows x 8 chunks = 512 cp, 4 per thread
#pragma unroll
    for (int it = 0; it < 4; it++) {
        const int i = tid + it * 128;
        const int r = i >> 3, c8 = (i & 7) * 8;
        CP_ASYNC16(sQb + 2u * (r * FSTR + c8),
                   qkv + base + (size_t)(q0 + r) * C3 + hoff + c8);
    }
    CP_COMMIT();

#define KV_STAGE(bufi, kt)                                                     \
    do {                                                                       \
        const uint32_t soK = sKb[bufi];                                        \
        const uint32_t soV = sVb[bufi];                                        \
        const __half* srcb = qkv + base + (size_t)((kt) * 64) * C3 + hoff;     \
        _Pragma("unroll")                                                      \
        for (int it = 0; it < 4; it++) {                                       \
            const int i = tid + it * 128;                                      \
            const int r = i >> 3, c8 = (i & 7) * 8;                            \
            CP_ASYNC16(soK + 2u * (r * FSTR + c8),                             \
                       srcb + (size_t)r * C3 + DIM + c8);                      \
            CP_ASYNC16(soV + 2u * (r * FSTR + c8),                             \
                       srcb + (size_t)r * C3 + 2 * DIM + c8);                  \
        }                                                                      \
        CP_COMMIT();                                                           \
    } while (0)

    KV_STAGE(0, 0);

    // Wait for Q (KV group 0 may stay pending), load Q fragments
    CP_WAIT1();
    __syncthreads();
    uint32_t aq[4][4];
#pragma unroll
    for (int kk = 0; kk < 4; kk++)
        ldsm_x4(aq[kk][0], aq[kk][1], aq[kk][2], aq[kk][3],
                sQb + 2u * ((warp * 16 + ar) * FSTR + kk * 16 + ak));

    float accO[8][4];
#pragma unroll
    for (int i = 0; i < 8; i++)
#pragma unroll
        for (int j = 0; j < 4; j++) accO[i][j] = 0.f;
    float m0 = -INFINITY, m1 = -INFINITY, l0 = 0.f, l1 = 0.f;

    for (int kt = 0; kt < 16; kt++) {
        const int buf = kt & 1;
        if (kt + 1 < 16) {
            KV_STAGE(buf ^ 1, kt + 1);
            CP_WAIT1();
        } else {
            CP_WAIT0();
        }
        __syncthreads();

        // S = Q * K^T
        float accS[8][4];
#pragma unroll
        for (int i = 0; i < 8; i++)
#pragma unroll
            for (int j = 0; j < 4; j++) accS[i][j] = 0.f;
#pragma unroll
        for (int kk = 0; kk < 4; kk++) {
#pragma unroll
            for (int p = 0; p < 4; p++) {
                uint32_t b0, b1, b2, b3;
                ldsm_x4(b0, b1, b2, b3,
                        sKb[buf] + 2u * ((p * 16 + br) * FSTR + kk * 16 + bk));
                mma_f16(accS[2 * p],     aq[kk], b0, b1);
                mma_f16(accS[2 * p + 1], aq[kk], b2, b3);
            }
        }
#pragma unroll
        for (int nt = 0; nt < 8; nt++) {
            accS[nt][0] *= qscale; accS[nt][1] *= qscale;
            accS[nt][2] *= qscale; accS[nt][3] *= qscale;
        }

        // Online softmax (rows g, g+8), base-2 domain
        float r0 = -INFINITY, r1 = -INFINITY;
#pragma unroll
        for (int nt = 0; nt < 8; nt++) {
            r0 = fmaxf(r0, fmaxf(accS[nt][0], accS[nt][1]));
            r1 = fmaxf(r1, fmaxf(accS[nt][2], accS[nt][3]));
        }
        r0 = fmaxf(r0, __shfl_xor_sync(0xffffffffu, r0, 1));
        r0 = fmaxf(r0, __shfl_xor_sync(0xffffffffu, r0, 2));
        r1 = fmaxf(r1, __shfl_xor_sync(0xffffffffu, r1, 1));
        r1 = fmaxf(r1, __shfl_xor_sync(0xffffffffu, r1, 2));
        const float mn0 = fmaxf(m0, r0);
        const float mn1 = fmaxf(m1, r1);
        const float al0 = exp2f(m0 - mn0);
        const float al1 = exp2f(m1 - mn1);
        float rs0 = 0.f, rs1 = 0.f;

        // P as A-fragments directly (C-frag of S == A-frag of P identity)
        uint32_t phA[8], phB[8];
#pragma unroll
        for (int nt = 0; nt < 8; nt++) {
            __half2 h01 = __floats2half2_rn(exp2f(accS[nt][0] - mn0),
                                            exp2f(accS[nt][1] - mn0));
            __half2 h23 = __floats2half2_rn(exp2f(accS[nt][2] - mn1),
                                            exp2f(accS[nt][3] - mn1));
            float2 f01 = __half22float2(h01);
            float2 f23 = __half22float2(h23);
            rs0 += f01.x + f01.y;
            rs1 += f23.x + f23.y;
            phA[nt] = *(uint32_t*)&h01;
            phB[nt] = *(uint32_t*)&h23;
        }
        rs0 += __shfl_xor_sync(0xffffffffu, rs0, 1);
        rs0 += __shfl_xor_sync(0xffffffffu, rs0, 2);
        rs1 += __shfl_xor_sync(0xffffffffu, rs1, 1);
        rs1 += __shfl_xor_sync(0xffffffffu, rs1, 2);
        l0 = l0 * al0 + rs0;
        l1 = l1 * al1 + rs1;
        m0 = mn0; m1 = mn1;
#pragma unroll
        for (int nt = 0; nt < 8; nt++) {
            accO[nt][0] *= al0; accO[nt][1] *= al0;
            accO[nt][2] *= al1; accO[nt][3] *= al1;
        }

        // O += P V (P from registers; V: B-frag via ldmatrix.trans)
#pragma unroll
        for (int kk = 0; kk < 4; kk++) {
            uint32_t ap[4];
            ap[0] = phA[2 * kk];
            ap[1] = phB[2 * kk];
            ap[2] = phA[2 * kk + 1];
            ap[3] = phB[2 * kk + 1];
#pragma unroll
            for (int p = 0; p < 4; p++) {
                uint32_t v0, v1, v2, v3;
                ldsm_x4_trans(v0, v1, v2, v3,
                              sVb[buf] + 2u * ((kk * 16 + vj) * FSTR + p * 16 + vd));
                mma_f16(accO[2 * p],     ap, v0, v1);
                mma_f16(accO[2 * p + 1], ap, v2, v3);
            }
        }
        __syncthreads();  // readers done before buf overwritten next iter
    }

    // Epilogue: normalize, write fp16 att [B,T,C]
    const float inv0 = 1.f / l0;
    const float inv1 = 1.f / l1;
    const int r0w = q0 + warp * 16 + g;
    __half* o0 = att + (size_t)b * TSZ * DIM + (size_t)r0w * DIM + hoff;
    __half* o1 = o0 + (size_t)8 * DIM;
#pragma unroll
    for (int nt = 0; nt < 8; nt++) {
        __half2 v0 = __floats2half2_rn(accO[nt][0] * inv0, accO[nt][1] * inv0);
        __half2 v1 = __floats2half2_rn(accO[nt][2] * inv1, accO[nt][3] * inv1);
        *(uint32_t*)&o0[nt * 8 + 2 * t] = *(uint32_t*)&v0;
        *(uint32_t*)&o1[nt * 8 + 2 * t] = *(uint32_t*)&v1;
    }
}

// ---------------------------------------------------------------------------
extern "C" void kernel_launch(void* const* d_in, const int* in_sizes, int n_in,
                              void* d_out, int out_size) {
    const float* x     = (const float*)d_in[0];  // [4,1024,1024]
    const float* Wqkv  = (const float*)d_in[1];  // [3072,1024]
    const float* Wproj = (const float*)d_in[2];  // [1024,1024]
    const float* bproj = (const float*)d_in[3];  // [1024]
    float* out = (float*)d_out;                  // [4,1024,1024]

    __half *xh, *wqkvh, *wprojh, *qkvh, *atth;
    cudaGetSymbolAddress((void**)&xh, g_xh);
    cudaGetSymbolAddress((void**)&wqkvh, g_wqkvh);
    cudaGetSymbolAddress((void**)&wprojh, g_wprojh);
    cudaGetSymbolAddress((void**)&qkvh, g_qkvh);
    cudaGetSymbolAddress((void**)&atth, g_atth);

    cudaFuncSetAttribute(f16_gemm_wide,
                         cudaFuncAttributeMaxDynamicSharedMemorySize, GEMMW_SMEM);
    cudaFuncSetAttribute(f16_gemm_sq,
                         cudaFuncAttributeMaxDynamicSharedMemorySize, GEMMS_SMEM);
    cudaFuncSetAttribute(flash_f16,
                         cudaFuncAttributeMaxDynamicSharedMemorySize, FLASH_SMEM);

    // 0) fused fp32 -> fp16 conversion (x, Wqkv, Wproj)
    cvt3_f32_f16<<<(N_X + N_WQ + N_WP) / 2048, 256>>>(x, Wqkv, Wproj,
                                                      xh, wqkvh, wprojh);

    // 1) QKV projection -> fp16: [4096,1024] x [3072,1024]^T -> [4096,3072]
    f16_gemm_wide<<<dim3(C3 / 256, (BATCH * TSZ) / 128), 512, GEMMW_SMEM>>>(
        xh, wqkvh, qkvh, BATCH * TSZ, C3, DIM);

    // 2) Attention (fp16 in/out, register P, 64-row CTAs, 1024 blocks)
    flash_f16<<<dim3(TSZ / 64, BATCH * NHEAD), 128, FLASH_SMEM>>>(qkvh, atth);

    // 3) Output projection + bias -> fp32 out (R13 square, BK=32, 2 CTA/SM)
    f16_gemm_sq<<<dim3(DIM / 128, (BATCH * TSZ) / 128), 256, GEMMS_SMEM>>>(
        atth, wprojh, bproj, out, BATCH * TSZ, DIM, DIM);
}